// round 2
// baseline (speedup 1.0000x reference)
#include <cuda_runtime.h>
#include <cuda_bf16.h>

// Problem constants (fixed-shape problem)
#define NN   50000
#define EE   1600000
#define DIN  256
#define DH   128
#define DOUT 64

// ---------------- device scratch (static allocation is the sanctioned path) ----
__device__ float g_xw1[NN * DH];       // x @ W1
__device__ float g_h1 [NN * DH];       // relu(agg1)
__device__ float g_xw2[NN * DOUT];     // h1 @ W2
__device__ float g_deg [NN];
__device__ float g_dinv[NN];
__device__ int   g_cnt   [NN];
__device__ int   g_rowptr[NN + 1];
__device__ int   g_wptr  [NN];
__device__ int   g_src[EE];            // CSR-by-target: source node ids
__device__ float g_ewn[EE];            // dinv[src] * w  per edge (CSR order)

// ---------------- setup kernels ------------------------------------------------
__global__ void init_kernel() {
    int i = blockIdx.x * blockDim.x + threadIdx.x;
    if (i < NN) { g_cnt[i] = 0; g_deg[i] = 1.0f; /* self-loop weight */ }
}

__global__ void count_kernel(const int* __restrict__ col, const float* __restrict__ w) {
    int e = blockIdx.x * blockDim.x + threadIdx.x;
    if (e < EE) {
        int c = __ldg(&col[e]);
        atomicAdd(&g_cnt[c], 1);
        atomicAdd(&g_deg[c], __ldg(&w[e]));
    }
}

__global__ void dinv_kernel() {
    int i = blockIdx.x * blockDim.x + threadIdx.x;
    if (i < NN) g_dinv[i] = rsqrtf(g_deg[i]);   // deg >= 1 always (self loop)
}

// single-block exclusive scan over g_cnt -> g_rowptr / g_wptr (1024 threads)
__global__ void scan_kernel() {
    __shared__ int warpsum[32];
    __shared__ int warpoff[32];
    __shared__ int s_carry;
    int tid = threadIdx.x, lane = tid & 31, wid = tid >> 5;
    if (tid == 0) s_carry = 0;
    __syncthreads();
    for (int base = 0; base < NN; base += 1024) {
        int i = base + tid;
        int v = (i < NN) ? g_cnt[i] : 0;
        int incl = v;
        #pragma unroll
        for (int o = 1; o < 32; o <<= 1) {
            int t = __shfl_up_sync(0xffffffff, incl, o);
            if (lane >= o) incl += t;
        }
        if (lane == 31) warpsum[wid] = incl;
        __syncthreads();
        if (wid == 0) {
            int s = warpsum[lane];
            int si = s;
            #pragma unroll
            for (int o = 1; o < 32; o <<= 1) {
                int t = __shfl_up_sync(0xffffffff, si, o);
                if (lane >= o) si += t;
            }
            warpoff[lane] = si - s;   // exclusive across warps
        }
        __syncthreads();
        int carry = s_carry;
        int ex = carry + warpoff[wid] + incl - v;
        if (i < NN) { g_rowptr[i] = ex; g_wptr[i] = ex; }
        __syncthreads();              // everyone read s_carry before update
        if (tid == 1023) s_carry = carry + warpoff[31] + incl;  // += chunk total
        __syncthreads();
    }
    if (threadIdx.x == 0) g_rowptr[NN] = s_carry;
}

__global__ void scatter_kernel(const int* __restrict__ row, const int* __restrict__ col,
                               const float* __restrict__ w) {
    int e = blockIdx.x * blockDim.x + threadIdx.x;
    if (e < EE) {
        int c = __ldg(&col[e]);
        int r = __ldg(&row[e]);
        int p = atomicAdd(&g_wptr[c], 1);
        g_src[p] = r;
        g_ewn[p] = __ldg(&w[e]) * g_dinv[r];
    }
}

// ---------------- SGEMM: C[M,Nc] = A[M,K] @ B[K,Nc], row-major, fp32 ----------
// BM=64, BN=64, BK=16, 256 threads, 4x4 microtile per thread.
__global__ __launch_bounds__(256) void sgemm_kernel(
    const float* __restrict__ A, const float* __restrict__ B, float* __restrict__ C,
    int M, int K, int Nc)
{
    __shared__ __align__(16) float As[16][64];   // transposed: As[k][m]
    __shared__ __align__(16) float Bs[16][64];
    int tid = threadIdx.x;
    int tx = tid & 15;            // 0..15 -> 4 cols each
    int ty = tid >> 4;            // 0..15 -> 4 rows each
    int rowBase = blockIdx.y * 64;
    int colBase = blockIdx.x * 64;

    int aRow = (tid * 4) >> 4;    // 0..63
    int aCol = (tid * 4) & 15;    // 0,4,8,12
    int bRow = (tid * 4) >> 6;    // 0..15
    int bCol = (tid * 4) & 63;

    float acc[4][4];
    #pragma unroll
    for (int i = 0; i < 4; i++)
        #pragma unroll
        for (int j = 0; j < 4; j++) acc[i][j] = 0.f;

    for (int kk = 0; kk < K; kk += 16) {
        float4 av = make_float4(0.f, 0.f, 0.f, 0.f);
        int gr = rowBase + aRow;
        if (gr < M) av = *(const float4*)&A[(size_t)gr * K + kk + aCol];
        As[aCol + 0][aRow] = av.x;
        As[aCol + 1][aRow] = av.y;
        As[aCol + 2][aRow] = av.z;
        As[aCol + 3][aRow] = av.w;
        float4 bv = *(const float4*)&B[(size_t)(kk + bRow) * Nc + colBase + bCol];
        *(float4*)&Bs[bRow][bCol] = bv;
        __syncthreads();
        #pragma unroll
        for (int k = 0; k < 16; k++) {
            float4 a = *(const float4*)&As[k][ty * 4];
            float4 b = *(const float4*)&Bs[k][tx * 4];
            float ar[4] = {a.x, a.y, a.z, a.w};
            float br[4] = {b.x, b.y, b.z, b.w};
            #pragma unroll
            for (int i = 0; i < 4; i++)
                #pragma unroll
                for (int j = 0; j < 4; j++)
                    acc[i][j] += ar[i] * br[j];
        }
        __syncthreads();
    }
    #pragma unroll
    for (int i = 0; i < 4; i++) {
        int gr = rowBase + ty * 4 + i;
        if (gr < M) {
            float4 v = make_float4(acc[i][0], acc[i][1], acc[i][2], acc[i][3]);
            *(float4*)&C[(size_t)gr * Nc + colBase + tx * 4] = v;
        }
    }
}

// ---------------- aggregation: out[i,f] = dinv[i]*sum_e(ewn*xw[src,f])
//                                + dinv[i]^2*xw[i,f] + bias[f]  (+relu / +log_softmax)
template<int D, bool RELU, bool SOFTMAX>
__global__ void aggregate_kernel(const float* __restrict__ xw,
                                 const float* __restrict__ bias,
                                 float* __restrict__ out)
{
    int node = blockIdx.x;
    int f = threadIdx.x;                 // D threads
    __shared__ int   s_src[D];
    __shared__ float s_w[D];
    int p0 = g_rowptr[node], p1 = g_rowptr[node + 1];
    float di = g_dinv[node];
    float acc = 0.f;
    for (int base = p0; base < p1; base += D) {
        int idx = base + f;
        if (idx < p1) { s_src[f] = g_src[idx]; s_w[f] = g_ewn[idx]; }
        __syncthreads();
        int c = min(D, p1 - base);
        #pragma unroll 4
        for (int j = 0; j < c; j++)
            acc += s_w[j] * __ldg(&xw[(size_t)s_src[j] * D + f]);
        __syncthreads();
    }
    float r = di * acc + di * di * __ldg(&xw[(size_t)node * D + f]) + bias[f];
    if (RELU) r = fmaxf(r, 0.f);
    if (SOFTMAX) {
        __shared__ float red[D];
        red[f] = r; __syncthreads();
        #pragma unroll
        for (int s = D / 2; s > 0; s >>= 1) {
            if (f < s) red[f] = fmaxf(red[f], red[f + s]);
            __syncthreads();
        }
        float m = red[0]; __syncthreads();
        red[f] = expf(r - m); __syncthreads();
        #pragma unroll
        for (int s = D / 2; s > 0; s >>= 1) {
            if (f < s) red[f] += red[f + s];
            __syncthreads();
        }
        r = r - m - logf(red[0]);
    }
    out[(size_t)node * D + f] = r;
}

// ---------------- launch -------------------------------------------------------
extern "C" void kernel_launch(void* const* d_in, const int* in_sizes, int n_in,
                              void* d_out, int out_size)
{
    const float* x  = (const float*)d_in[0];
    const int*   ei = (const int*)  d_in[1];
    const float* ew = (const float*)d_in[2];
    const float* W1 = (const float*)d_in[3];
    const float* b1 = (const float*)d_in[4];
    const float* W2 = (const float*)d_in[5];
    const float* b2 = (const float*)d_in[6];
    float* out = (float*)d_out;

    const int* row = ei;          // sources
    const int* col = ei + EE;     // targets

    void *p_xw1, *p_h1, *p_xw2;
    cudaGetSymbolAddress(&p_xw1, g_xw1);
    cudaGetSymbolAddress(&p_h1,  g_h1);
    cudaGetSymbolAddress(&p_xw2, g_xw2);
    float* xw1 = (float*)p_xw1;
    float* h1  = (float*)p_h1;
    float* xw2 = (float*)p_xw2;

    const int TB = 256;
    // CSR build + degree norm
    init_kernel   <<<(NN + TB - 1) / TB, TB>>>();
    count_kernel  <<<(EE + TB - 1) / TB, TB>>>(col, ew);
    dinv_kernel   <<<(NN + TB - 1) / TB, TB>>>();
    scan_kernel   <<<1, 1024>>>();
    scatter_kernel<<<(EE + TB - 1) / TB, TB>>>(row, col, ew);

    // layer 1
    {
        dim3 grid(DH / 64, (NN + 63) / 64);
        sgemm_kernel<<<grid, 256>>>(x, W1, xw1, NN, DIN, DH);
    }
    aggregate_kernel<DH, true, false><<<NN, DH>>>(xw1, b1, h1);

    // layer 2 + fused log_softmax
    {
        dim3 grid(DOUT / 64, (NN + 63) / 64);
        sgemm_kernel<<<grid, 256>>>(h1, W2, xw2, NN, DH, DOUT);
    }
    aggregate_kernel<DOUT, false, true><<<NN, DOUT>>>(xw2, b2, out);
}

// round 3
// speedup vs baseline: 1.2180x; 1.2180x over previous
#include <cuda_runtime.h>
#include <cuda_bf16.h>

// Problem constants (fixed-shape problem)
#define NN   50000
#define EE   1600000
#define DIN  256
#define DH   128
#define DOUT 64

#define SCAN_CHUNK 1024
#define SCAN_NBLK  ((NN + SCAN_CHUNK - 1) / SCAN_CHUNK)   // 49

// ---------------- device scratch ----------------------------------------------
__device__ float g_xw1[NN * DH];       // x @ W1
__device__ float g_h1 [NN * DH];       // relu(agg1)
__device__ float g_xw2[NN * DOUT];     // h1 @ W2
__device__ float g_deg [NN];
__device__ float g_dinv[NN];
__device__ int   g_cnt   [NN];
__device__ int   g_rowptr[NN + 1];
__device__ int   g_wptr  [NN];
__device__ int   g_blocksum[SCAN_NBLK];
__device__ int   g_blockoff[SCAN_NBLK];
__device__ int   g_src[EE];            // CSR-by-target: source node ids
__device__ float g_ewn[EE];            // dinv[src] * w  per edge (CSR order)

// ---------------- setup kernels ------------------------------------------------
__global__ void init_kernel() {
    int i = blockIdx.x * blockDim.x + threadIdx.x;
    if (i < NN) { g_cnt[i] = 0; g_deg[i] = 1.0f; /* self-loop weight */ }
}

__global__ void count_kernel(const int* __restrict__ col, const float* __restrict__ w) {
    int e = blockIdx.x * blockDim.x + threadIdx.x;
    if (e < EE) {
        int c = __ldg(&col[e]);
        atomicAdd(&g_cnt[c], 1);
        atomicAdd(&g_deg[c], __ldg(&w[e]));
    }
}

__global__ void dinv_kernel() {
    int i = blockIdx.x * blockDim.x + threadIdx.x;
    if (i < NN) g_dinv[i] = rsqrtf(g_deg[i]);   // deg >= 1 always (self loop)
}

// ---- multi-block scan: phase A — per-block exclusive scan + block totals ------
__global__ __launch_bounds__(SCAN_CHUNK) void scanA_kernel() {
    __shared__ int warpsum[32];
    __shared__ int warpoff[32];
    int tid = threadIdx.x, lane = tid & 31, wid = tid >> 5;
    int gid = blockIdx.x * SCAN_CHUNK + tid;
    int v = (gid < NN) ? g_cnt[gid] : 0;
    int incl = v;
    #pragma unroll
    for (int o = 1; o < 32; o <<= 1) {
        int t = __shfl_up_sync(0xffffffffu, incl, o);
        if (lane >= o) incl += t;
    }
    if (lane == 31) warpsum[wid] = incl;
    __syncthreads();
    if (wid == 0) {
        int s = warpsum[lane];
        int si = s;
        #pragma unroll
        for (int o = 1; o < 32; o <<= 1) {
            int t = __shfl_up_sync(0xffffffffu, si, o);
            if (lane >= o) si += t;
        }
        warpoff[lane] = si - s;   // exclusive across warps
    }
    __syncthreads();
    int ex = warpoff[wid] + incl - v;   // block-local exclusive
    if (gid < NN) g_rowptr[gid] = ex;
    if (tid == SCAN_CHUNK - 1) g_blocksum[blockIdx.x] = ex + v;  // block total
}

// ---- phase B — tiny sequential scan of 49 block totals -----------------------
__global__ void scanB_kernel() {
    if (threadIdx.x == 0) {
        int run = 0;
        #pragma unroll
        for (int b = 0; b < SCAN_NBLK; b++) {
            g_blockoff[b] = run;
            run += g_blocksum[b];
        }
    }
}

// ---- phase C — add block offsets, init wptr ----------------------------------
__global__ void scanC_kernel() {
    int i = blockIdx.x * blockDim.x + threadIdx.x;
    if (i < NN) {
        int v = g_rowptr[i] + g_blockoff[i / SCAN_CHUNK];
        g_rowptr[i] = v;
        g_wptr[i]   = v;
    }
    if (i == 0) g_rowptr[NN] = EE;   // total edge count is a constant
}

__global__ void scatter_kernel(const int* __restrict__ row, const int* __restrict__ col,
                               const float* __restrict__ w) {
    int e = blockIdx.x * blockDim.x + threadIdx.x;
    if (e < EE) {
        int c = __ldg(&col[e]);
        int r = __ldg(&row[e]);
        int p = atomicAdd(&g_wptr[c], 1);
        g_src[p] = r;
        g_ewn[p] = __ldg(&w[e]) * g_dinv[r];
    }
}

// ---------------- SGEMM: C[M,Nc] = A[M,K] @ B[K,Nc], row-major, fp32 ----------
__global__ __launch_bounds__(256) void sgemm_kernel(
    const float* __restrict__ A, const float* __restrict__ B, float* __restrict__ C,
    int M, int K, int Nc)
{
    __shared__ __align__(16) float As[16][64];   // transposed: As[k][m]
    __shared__ __align__(16) float Bs[16][64];
    int tid = threadIdx.x;
    int tx = tid & 15;
    int ty = tid >> 4;
    int rowBase = blockIdx.y * 64;
    int colBase = blockIdx.x * 64;

    int aRow = (tid * 4) >> 4;
    int aCol = (tid * 4) & 15;
    int bRow = (tid * 4) >> 6;
    int bCol = (tid * 4) & 63;

    float acc[4][4];
    #pragma unroll
    for (int i = 0; i < 4; i++)
        #pragma unroll
        for (int j = 0; j < 4; j++) acc[i][j] = 0.f;

    for (int kk = 0; kk < K; kk += 16) {
        float4 av = make_float4(0.f, 0.f, 0.f, 0.f);
        int gr = rowBase + aRow;
        if (gr < M) av = *(const float4*)&A[(size_t)gr * K + kk + aCol];
        As[aCol + 0][aRow] = av.x;
        As[aCol + 1][aRow] = av.y;
        As[aCol + 2][aRow] = av.z;
        As[aCol + 3][aRow] = av.w;
        float4 bv = *(const float4*)&B[(size_t)(kk + bRow) * Nc + colBase + bCol];
        *(float4*)&Bs[bRow][bCol] = bv;
        __syncthreads();
        #pragma unroll
        for (int k = 0; k < 16; k++) {
            float4 a = *(const float4*)&As[k][ty * 4];
            float4 b = *(const float4*)&Bs[k][tx * 4];
            float ar[4] = {a.x, a.y, a.z, a.w};
            float br[4] = {b.x, b.y, b.z, b.w};
            #pragma unroll
            for (int i = 0; i < 4; i++)
                #pragma unroll
                for (int j = 0; j < 4; j++)
                    acc[i][j] += ar[i] * br[j];
        }
        __syncthreads();
    }
    #pragma unroll
    for (int i = 0; i < 4; i++) {
        int gr = rowBase + ty * 4 + i;
        if (gr < M) {
            float4 v = make_float4(acc[i][0], acc[i][1], acc[i][2], acc[i][3]);
            *(float4*)&C[(size_t)gr * Nc + colBase + tx * 4] = v;
        }
    }
}

// ---------------- warp-per-node aggregation -----------------------------------
// out[i,f] = dinv[i]*sum_e(ewn*xw[src,f]) + dinv[i]^2*xw[i,f] + bias[f]
// D=128: float4 per lane.  D=64: float2 per lane + warp log_softmax.
template<int D, bool RELU, bool SOFTMAX>
__global__ __launch_bounds__(256) void aggregate_warp_kernel(
    const float* __restrict__ xw, const float* __restrict__ bias,
    float* __restrict__ out)
{
    constexpr int WPB = 8;               // warps per block
    int wid  = threadIdx.x >> 5;
    int lane = threadIdx.x & 31;
    int node = blockIdx.x * WPB + wid;
    if (node >= NN) return;

    int p0 = g_rowptr[node], p1 = g_rowptr[node + 1];
    float di = g_dinv[node];

    if constexpr (D == 128) {
        const float4* xw4 = (const float4*)xw;
        float4 acc = make_float4(0.f, 0.f, 0.f, 0.f);
        for (int base = p0; base < p1; base += 32) {
            int idx = base + lane;
            int s = 0; float wv = 0.f;
            if (idx < p1) { s = g_src[idx]; wv = g_ewn[idx]; }
            int c = min(32, p1 - base);
            #pragma unroll 4
            for (int j = 0; j < c; j++) {
                int   sj = __shfl_sync(0xffffffffu, s,  j);
                float wj = __shfl_sync(0xffffffffu, wv, j);
                float4 v = __ldg(&xw4[(size_t)sj * 32 + lane]);
                acc.x += wj * v.x; acc.y += wj * v.y;
                acc.z += wj * v.z; acc.w += wj * v.w;
            }
        }
        float4 self = __ldg(&xw4[(size_t)node * 32 + lane]);
        float4 bv   = __ldg(&((const float4*)bias)[lane]);
        float d2 = di * di;
        float4 r;
        r.x = di * acc.x + d2 * self.x + bv.x;
        r.y = di * acc.y + d2 * self.y + bv.y;
        r.z = di * acc.z + d2 * self.z + bv.z;
        r.w = di * acc.w + d2 * self.w + bv.w;
        if (RELU) {
            r.x = fmaxf(r.x, 0.f); r.y = fmaxf(r.y, 0.f);
            r.z = fmaxf(r.z, 0.f); r.w = fmaxf(r.w, 0.f);
        }
        ((float4*)out)[(size_t)node * 32 + lane] = r;
    } else {
        // D == 64
        const float2* xw2 = (const float2*)xw;
        float2 acc = make_float2(0.f, 0.f);
        for (int base = p0; base < p1; base += 32) {
            int idx = base + lane;
            int s = 0; float wv = 0.f;
            if (idx < p1) { s = g_src[idx]; wv = g_ewn[idx]; }
            int c = min(32, p1 - base);
            #pragma unroll 4
            for (int j = 0; j < c; j++) {
                int   sj = __shfl_sync(0xffffffffu, s,  j);
                float wj = __shfl_sync(0xffffffffu, wv, j);
                float2 v = __ldg(&xw2[(size_t)sj * 32 + lane]);
                acc.x += wj * v.x; acc.y += wj * v.y;
            }
        }
        float2 self = __ldg(&xw2[(size_t)node * 32 + lane]);
        float2 bv   = __ldg(&((const float2*)bias)[lane]);
        float d2 = di * di;
        float rx = di * acc.x + d2 * self.x + bv.x;
        float ry = di * acc.y + d2 * self.y + bv.y;
        if (RELU) { rx = fmaxf(rx, 0.f); ry = fmaxf(ry, 0.f); }
        if (SOFTMAX) {
            float m = fmaxf(rx, ry);
            #pragma unroll
            for (int o = 16; o > 0; o >>= 1)
                m = fmaxf(m, __shfl_xor_sync(0xffffffffu, m, o));
            float sum = expf(rx - m) + expf(ry - m);
            #pragma unroll
            for (int o = 16; o > 0; o >>= 1)
                sum += __shfl_xor_sync(0xffffffffu, sum, o);
            float ls = m + logf(sum);
            rx -= ls; ry -= ls;
        }
        ((float2*)out)[(size_t)node * 32 + lane] = make_float2(rx, ry);
    }
}

// ---------------- launch -------------------------------------------------------
extern "C" void kernel_launch(void* const* d_in, const int* in_sizes, int n_in,
                              void* d_out, int out_size)
{
    const float* x  = (const float*)d_in[0];
    const int*   ei = (const int*)  d_in[1];
    const float* ew = (const float*)d_in[2];
    const float* W1 = (const float*)d_in[3];
    const float* b1 = (const float*)d_in[4];
    const float* W2 = (const float*)d_in[5];
    const float* b2 = (const float*)d_in[6];
    float* out = (float*)d_out;

    const int* row = ei;          // sources
    const int* col = ei + EE;     // targets

    void *p_xw1, *p_h1, *p_xw2;
    cudaGetSymbolAddress(&p_xw1, g_xw1);
    cudaGetSymbolAddress(&p_h1,  g_h1);
    cudaGetSymbolAddress(&p_xw2, g_xw2);
    float* xw1 = (float*)p_xw1;
    float* h1  = (float*)p_h1;
    float* xw2 = (float*)p_xw2;

    const int TB = 256;
    // CSR build + degree norm
    init_kernel   <<<(NN + TB - 1) / TB, TB>>>();
    count_kernel  <<<(EE + TB - 1) / TB, TB>>>(col, ew);
    dinv_kernel   <<<(NN + TB - 1) / TB, TB>>>();
    scanA_kernel  <<<SCAN_NBLK, SCAN_CHUNK>>>();
    scanB_kernel  <<<1, 32>>>();
    scanC_kernel  <<<(NN + TB - 1) / TB, TB>>>();
    scatter_kernel<<<(EE + TB - 1) / TB, TB>>>(row, col, ew);

    // layer 1
    {
        dim3 grid(DH / 64, (NN + 63) / 64);
        sgemm_kernel<<<grid, 256>>>(x, W1, xw1, NN, DIN, DH);
    }
    aggregate_warp_kernel<DH, true, false><<<(NN + 7) / 8, 256>>>(xw1, b1, h1);

    // layer 2 + fused log_softmax
    {
        dim3 grid(DOUT / 64, (NN + 63) / 64);
        sgemm_kernel<<<grid, 256>>>(h1, W2, xw2, NN, DH, DOUT);
    }
    aggregate_warp_kernel<DOUT, false, true><<<(NN + 7) / 8, 256>>>(xw2, b2, out);
}